// round 13
// baseline (speedup 1.0000x reference)
#include <cuda_runtime.h>
#include <math.h>

#define BB   1024
#define TT   64
#define FF   18
#define UU   128
#define G3   384

// ---- device scratch (allocation-free, all row-owned or write-before-read) ----
__device__ float  g_xz[(size_t)BB * TT * 3 * UU];  // xz spilled for deferred steps
__device__ float  g_h[(size_t)BB * TT * UU];       // chain states keyed by (b, slot)
__device__ float  g_hlast[(size_t)BB * UU];        // h after step T-1
__device__ float2 g_rkzr[UU * UU];                 // packed rec_kernel (z,r)
__device__ float  g_rkh[UU * UU];                  // rec_kernel h-gate
__device__ int    g_meta[BB * TT];                 // slot | (round<<8), per (b,t)
__device__ short  g_rlist[BB][TT];                 // round-1 step t's, per row
__device__ int    g_rcnt[BB];                      // round-1 count, per row

// ============================================================================
// main: per row — rk packing (b<128), slot/chain analysis, init gather+flags,
// xz compute fused with the round-0 epilogue; round>=1 steps spill xz.
// ============================================================================
__global__ __launch_bounds__(128)
void rnn_main(const float* __restrict__ inputs,      // [B, T, F]
              const float* __restrict__ sync_states, // [NIDS, B, U]
              const float* __restrict__ wk,          // [F, 3U]
              const float* __restrict__ rk,          // [U, 3U]
              const float* __restrict__ bias)        // [3U]
{
    __shared__ float2 xd[TT * FF];       // x duplicated (x,x) for f32x2
    __shared__ int    ids_sh[TT];
    __shared__ int    slot_sh[TT];       // slot | round<<8 | repeat-later<<17

    const int b = blockIdx.x, u = threadIdx.x;

    // fold rk packing into the first 128 CTAs (1 entry/thread; rounds run later)
    if (b < UU) {
        const int i = b * 128 + u;                   // covers UU*UU exactly
        const int k = i >> 7, uu = i & 127;
        g_rkzr[i] = make_float2(rk[k * G3 + uu], rk[k * G3 + UU + uu]);
        g_rkh[i]  = rk[k * G3 + 2 * UU + uu];
    }

    for (int i = u; i < TT * FF; i += 128) {
        const float v = inputs[(size_t)b * TT * FF + i];
        xd[i] = make_float2(v, v);
    }

    // input-to-hidden weights in registers: (wz,wr) packed + wh scalar
    unsigned long long wzr[FF];
    float wh[FF];
#pragma unroll
    for (int k = 0; k < FF; k++) {
        const float z = wk[k * G3 + u], r = wk[k * G3 + UU + u];
        asm("mov.b64 %0, {%1, %2};" : "=l"(wzr[k]) : "f"(z), "f"(r));
        wh[k] = wk[k * G3 + 2 * UU + u];
    }
    unsigned long long bzr;
    {
        const float z = bias[u], r = bias[UU + u];
        asm("mov.b64 %0, {%1, %2};" : "=l"(bzr) : "f"(z), "f"(r));
    }
    const float bh = bias[2 * UU + u];
    __syncthreads();

    if (u < TT) ids_sh[u] = (int)xd[u * FF].x;
    __syncthreads();

    // first-occurrence slot + occurrence position
    if (u < TT) {
        const int myid = ids_sh[u];
        int s = -1, pos = 0;
        for (int j = 0; j < u; j++)
            if (ids_sh[j] == myid) { if (s < 0) s = j; pos++; }
        if (s < 0) s = u;
        slot_sh[u] = s | (pos << 8);
    }
    __syncthreads();
    if (u < TT) {
        const int sr = slot_sh[u];
        if (sr >> 8) atomicOr(&slot_sh[sr & 0xff], 1 << 17);  // slot repeats later
    }
    __syncthreads();

    // gather initial states (first occurrences only), 16-deep MLP;
    // flag nonzero chains (bit16)
    for (int t0 = 0; t0 < TT; t0 += 16) {
        float v[16];
        int   fo[16];
#pragma unroll
        for (int j = 0; j < 16; j++) {
            const int t = t0 + j;
            fo[j] = ((slot_sh[t] & 0xff) == t);
            v[j] = fo[j] ? __ldcs(&sync_states[((size_t)ids_sh[t] * BB + b) * UU + u])
                         : 0.0f;
        }
#pragma unroll
        for (int j = 0; j < 16; j++) {
            const int t = t0 + j;
            if (fo[j] && v[j] != 0.0f) atomicOr(&slot_sh[t], 1 << 16);
        }
    }
    __syncthreads();

    // finalize round = pos + (chain init nonzero); write meta
    int newv = 0;
    if (u < TT) {
        const int sr   = slot_sh[u];
        const int slot = sr & 0xff;
        const int pos  = (sr >> 8) & 0xff;
        const int r    = pos + ((slot_sh[slot] >> 16) & 1);
        newv = slot | (r << 8) | (sr & (1 << 17));
        g_meta[b * TT + u] = slot | (r << 8);
    }
    __syncthreads();
    if (u < TT) slot_sh[u] = newv;
    __syncthreads();

    // per-row round-1 list (single thread, deterministic, no global atomics)
    if (u == 0) {
        int c = 0;
        for (int t = 0; t < TT; t++)
            if (((slot_sh[t] >> 8) & 0xff) == 1) g_rlist[b][c++] = (short)t;
        g_rcnt[b] = c;
    }

    // nonzero-init chains need h0 staged (rare; re-load is fine)
    for (int t = 0; t < TT; t++) {
        const int sr = slot_sh[t];
        if ((sr & 0xff) == t && ((sr >> 8) & 0xff) >= 1)
            g_h[((size_t)b * TT + t) * UU + u] =
                sync_states[((size_t)ids_sh[t] * BB + b) * UU + u];
    }

    // main fused loop: xz compute + inline epilogue for round-0 steps
#pragma unroll 2
    for (int t = 0; t < TT; t++) {
        const int sr   = slot_sh[t];
        const int slot = sr & 0xff;
        const int r    = (sr >> 8) & 0xff;

        const unsigned long long* xp = (const unsigned long long*)(xd + t * FF);
        unsigned long long acc = bzr;
        float ah = bh;
#pragma unroll
        for (int k = 0; k < FF; k++) {
            const unsigned long long xb = xp[k];
            asm("fma.rn.f32x2 %0, %1, %2, %0;" : "+l"(acc) : "l"(xb), "l"(wzr[k]));
            ah = fmaf(__uint_as_float((unsigned int)xb), wh[k], ah);
        }
        float az, ar;
        asm("mov.b64 {%0, %1}, %2;" : "=f"(az), "=f"(ar) : "l"(acc));

        if (r == 0) {                         // h == 0: closed-form epilogue
            const float z  = __saturatef(0.2f * az + 0.5f);
            const float e  = __expf(2.0f * ah);
            const float hh = 1.0f - __fdividef(2.0f, e + 1.0f);
            const float hn = (1.0f - z) * hh;
            if ((sr >> 17) & 1)               // only if this id repeats later
                g_h[((size_t)b * TT + slot) * UU + u] = hn;
            if (t == TT - 1) g_hlast[(size_t)b * UU + u] = hn;
        } else {                              // deferred: spill xz (L2-resident)
            float* p = g_xz + ((size_t)b * TT + t) * 3 * UU + u;
            p[0] = az; p[UU] = ar; p[2 * UU] = ah;
        }
    }
}

// ============================================================================
// round1: all chain-position-1 steps, grid-wide, independent. 2 CTAs per row
// stride that row's list; consecutive entries reuse L1-resident packed rk.
// ============================================================================
__global__ __launch_bounds__(128)
void round1_k()
{
    __shared__ float h_sh[UU];
    const int u  = threadIdx.x;
    const int b  = blockIdx.x >> 1;
    const int j0 = blockIdx.x & 1;
    const int n  = g_rcnt[b];

    for (int j = j0; j < n; j += 2) {
        const int t    = g_rlist[b][j];
        const int slot = g_meta[b * TT + t] & 0xff;   // hoisted before data loads

        // issue all independent loads back-to-back (xz triple + h), publish h
        const float* p  = g_xz + ((size_t)b * TT + t) * 3 * UU + u;
        const float az  = p[0], ar = p[UU], ah = p[2 * UU];
        const float h_u = g_h[((size_t)b * TT + slot) * UU + u];
        h_sh[u] = h_u;
        __syncthreads();

        float gz = 0.0f, gr = 0.0f, gh = 0.0f;
#pragma unroll 4
        for (int k = 0; k < UU; k++) {
            const float  hv = h_sh[k];
            const float2 w  = __ldg(&g_rkzr[k * UU + u]);
            gz = fmaf(hv, w.x, gz);
            gr = fmaf(hv, w.y, gr);
            gh = fmaf(hv, __ldg(&g_rkh[k * UU + u]), gh);
        }

        const float z   = __saturatef(0.2f * (az + gz) + 0.5f);
        const float rr  = __saturatef(0.2f * (ar + gr) + 0.5f);
        const float pre = ah + rr * gh;
        const float e2  = __expf(2.0f * pre);
        const float hh  = 1.0f - __fdividef(2.0f, e2 + 1.0f);
        const float hn  = z * h_u + (1.0f - z) * hh;

        __syncthreads();                      // protect h_sh before next entry
        g_h[((size_t)b * TT + slot) * UU + u] = hn;
        if (t == TT - 1) g_hlast[(size_t)b * UU + u] = hn;
    }
}

// ============================================================================
// head: serial cleanup for chain positions >= 2 (rare, ~40 rows grid-wide),
// then the dense head.
// ============================================================================
__global__ __launch_bounds__(128)
void head_k(const float* __restrict__ dw, const float* __restrict__ db,
            const float* __restrict__ ow, const float* __restrict__ ob,
            float* __restrict__ out)
{
    __shared__ float h_sh[UU];
    __shared__ int   meta_sh[TT];
    __shared__ float red[2];

    const int b = blockIdx.x, u = threadIdx.x;

    if (u < TT) meta_sh[u] = g_meta[b * TT + u];
    __syncthreads();

    int any = 0;
    for (int t = 0; t < TT; t++) any |= ((meta_sh[t] >> 8) > 1);

    float hl_local = 0.0f;
    int   hl_from_local = 0;
    if (any) {                                // uniform per block
        for (int t = 0; t < TT; t++) {
            if ((meta_sh[t] >> 8) > 1) {      // uniform per block
                const int slot = meta_sh[t] & 0xff;
                const float* p  = g_xz + ((size_t)b * TT + t) * 3 * UU + u;
                const float az  = p[0], ar = p[UU], ah = p[2 * UU];
                const float h_u = g_h[((size_t)b * TT + slot) * UU + u];
                h_sh[u] = h_u;
                __syncthreads();
                float gz = 0.0f, gr = 0.0f, gh = 0.0f;
#pragma unroll 4
                for (int k = 0; k < UU; k++) {
                    const float  hv = h_sh[k];
                    const float2 w  = __ldg(&g_rkzr[k * UU + u]);
                    gz = fmaf(hv, w.x, gz);
                    gr = fmaf(hv, w.y, gr);
                    gh = fmaf(hv, __ldg(&g_rkh[k * UU + u]), gh);
                }
                const float z   = __saturatef(0.2f * (az + gz) + 0.5f);
                const float rr  = __saturatef(0.2f * (ar + gr) + 0.5f);
                const float pre = ah + rr * gh;
                const float e2  = __expf(2.0f * pre);
                const float hh  = 1.0f - __fdividef(2.0f, e2 + 1.0f);
                const float hn  = z * h_u + (1.0f - z) * hh;
                __syncthreads();
                g_h[((size_t)b * TT + slot) * UU + u] = hn;
                if (t == TT - 1) { hl_local = hn; hl_from_local = 1; }
            }
        }
    }

    const float hl = hl_from_local ? hl_local : g_hlast[(size_t)b * UU + u];
    __syncthreads();
    h_sh[u] = hl;
    __syncthreads();

    if (u < 64) {
        float acc = db[u];
#pragma unroll 4
        for (int k = 0; k < UU; k++)
            acc = fmaf(h_sh[k], dw[k * 64 + u], acc);
        acc = fmaxf(acc, 0.0f) * ow[u];
#pragma unroll
        for (int o = 16; o; o >>= 1)
            acc += __shfl_down_sync(0xffffffff, acc, o);
        if ((u & 31) == 0) red[u >> 5] = acc;
    }
    __syncthreads();
    if (u == 0) {
        const float s = ob[0] + red[0] + red[1];
        out[b] = __fdividef(1.0f, 1.0f + __expf(-s));
    }
}

extern "C" void kernel_launch(void* const* d_in, const int* in_sizes, int n_in,
                              void* d_out, int out_size)
{
    const float* inputs      = (const float*)d_in[0];
    const float* sync_states = (const float*)d_in[1];
    const float* wk          = (const float*)d_in[2];
    const float* rk          = (const float*)d_in[3];
    const float* bias        = (const float*)d_in[4];
    const float* dw          = (const float*)d_in[5];
    const float* db          = (const float*)d_in[6];
    const float* ow          = (const float*)d_in[7];
    const float* ob          = (const float*)d_in[8];
    float* out = (float*)d_out;

    rnn_main<<<BB, 128>>>(inputs, sync_states, wk, rk, bias);
    round1_k<<<2 * BB, 128>>>();
    head_k<<<BB, 128>>>(dw, db, ow, ob, out);
}

// round 15
// speedup vs baseline: 1.0053x; 1.0053x over previous
#include <cuda_runtime.h>
#include <math.h>

#define BB   1024
#define TT   64
#define FF   18
#define XP   20          // padded x row: 5 aligned float4 loads
#define UU   128
#define G3   384

// ---- device scratch (allocation-free; row-owned or write-before-read) ----
__device__ float  g_xz[(size_t)BB * TT * 3 * UU];  // xz spilled for deferred steps
__device__ float  g_h[(size_t)BB * TT * UU];       // chain states keyed by (b, slot)
__device__ float  g_hlast[(size_t)BB * UU];        // h after step T-1 (round-0 case)
__device__ float2 g_rkzr[UU * UU];                 // packed rec_kernel (z,r)
__device__ float  g_rkh[UU * UU];                  // rec_kernel h-gate
__device__ int    g_meta[BB * TT];                 // slot | (round<<8), per (b,t)
__device__ int    g_nrep[BB];                      // # of round>=1 steps, per row

// ============================================================================
// main: per row — rk packing (b<128), slot/chain analysis, init gather+flags,
// then the fused loop. Round-0 steps need ONLY az and ah (r-gate multiplies
// gh==0), so the fast path is 36 scalar FFMAs; deferred steps compute all
// three gates (wr fetched from global — rare) and spill xz.
// ============================================================================
__global__ __launch_bounds__(128)
void rnn_main(const float* __restrict__ inputs,      // [B, T, F]
              const float* __restrict__ sync_states, // [NIDS, B, U]
              const float* __restrict__ wk,          // [F, 3U]
              const float* __restrict__ rk,          // [U, 3U]
              const float* __restrict__ bias)        // [3U]
{
    __shared__ float x_row[TT * XP];     // 5120 B, plain (no duplication)
    __shared__ int   ids_sh[TT];
    __shared__ int   slot_sh[TT];        // slot | round<<8 | repeat-later<<17

    const int b = blockIdx.x, u = threadIdx.x;

    // fold rk packing into the first 128 CTAs (1 entry/thread)
    if (b < UU) {
        const int i = b * 128 + u;                   // covers UU*UU exactly
        const int k = i >> 7, uu = i & 127;
        g_rkzr[i] = make_float2(rk[k * G3 + uu], rk[k * G3 + UU + uu]);
        g_rkh[i]  = rk[k * G3 + 2 * UU + uu];
    }

    for (int i = u; i < TT * FF; i += 128) {
        const int t = i / FF, k = i - t * FF;
        x_row[t * XP + k] = inputs[(size_t)b * TT * FF + i];
    }

    // input-to-hidden weights in registers: z and h gates only (36 regs)
    float wz[FF], wh[FF];
#pragma unroll
    for (int k = 0; k < FF; k++) {
        wz[k] = wk[k * G3 + u];
        wh[k] = wk[k * G3 + 2 * UU + u];
    }
    const float bz = bias[u], br = bias[UU + u], bh = bias[2 * UU + u];
    __syncthreads();

    if (u < TT) ids_sh[u] = (int)x_row[u * XP];
    __syncthreads();

    // first-occurrence slot + occurrence position
    if (u < TT) {
        const int myid = ids_sh[u];
        int s = -1, pos = 0;
        for (int j = 0; j < u; j++)
            if (ids_sh[j] == myid) { if (s < 0) s = j; pos++; }
        if (s < 0) s = u;
        slot_sh[u] = s | (pos << 8);
    }
    __syncthreads();
    if (u < TT) {
        const int sr = slot_sh[u];
        if (sr >> 8) atomicOr(&slot_sh[sr & 0xff], 1 << 17);  // slot repeats later
    }
    __syncthreads();

    // gather initial states (first occurrences only), 16-deep MLP;
    // flag nonzero chains (bit16)
    for (int t0 = 0; t0 < TT; t0 += 16) {
        float v[16];
        int   fo[16];
#pragma unroll
        for (int j = 0; j < 16; j++) {
            const int t = t0 + j;
            fo[j] = ((slot_sh[t] & 0xff) == t);
            v[j] = fo[j] ? __ldcs(&sync_states[((size_t)ids_sh[t] * BB + b) * UU + u])
                         : 0.0f;
        }
#pragma unroll
        for (int j = 0; j < 16; j++) {
            const int t = t0 + j;
            if (fo[j] && v[j] != 0.0f) atomicOr(&slot_sh[t], 1 << 16);
        }
    }
    __syncthreads();

    // finalize round = pos + (chain init nonzero); write meta
    int newv = 0;
    if (u < TT) {
        const int sr   = slot_sh[u];
        const int slot = sr & 0xff;
        const int pos  = (sr >> 8) & 0xff;
        const int r    = pos + ((slot_sh[slot] >> 16) & 1);
        newv = slot | (r << 8) | (sr & (1 << 17));
        g_meta[b * TT + u] = slot | (r << 8);
    }
    __syncthreads();
    if (u < TT) slot_sh[u] = newv;
    __syncthreads();

    if (u == 0) {                        // per-row deferred count for tail skip
        int c = 0;
        for (int t = 0; t < TT; t++) c += (((slot_sh[t] >> 8) & 0xff) != 0);
        g_nrep[b] = c;
    }

    // nonzero-init chains need h0 staged (rare; re-load is fine)
    for (int t = 0; t < TT; t++) {
        const int sr = slot_sh[t];
        if ((sr & 0xff) == t && ((sr >> 8) & 0xff) >= 1)
            g_h[((size_t)b * TT + t) * UU + u] =
                sync_states[((size_t)ids_sh[t] * BB + b) * UU + u];
    }

    // fused main loop
    for (int t = 0; t < TT; t++) {
        const int sr   = slot_sh[t];
        const int slot = sr & 0xff;
        const int r    = (sr >> 8) & 0xff;

        const float4 x0 = *(const float4*)(x_row + t * XP);
        const float4 x1 = *(const float4*)(x_row + t * XP + 4);
        const float4 x2 = *(const float4*)(x_row + t * XP + 8);
        const float4 x3 = *(const float4*)(x_row + t * XP + 12);
        const float2 x4 = *(const float2*)(x_row + t * XP + 16);
        const float xv[FF] = { x0.x, x0.y, x0.z, x0.w,  x1.x, x1.y, x1.z, x1.w,
                               x2.x, x2.y, x2.z, x2.w,  x3.x, x3.y, x3.z, x3.w,
                               x4.x, x4.y };

        float az = bz, ah = bh;
#pragma unroll
        for (int k = 0; k < FF; k++) {
            az = fmaf(xv[k], wz[k], az);
            ah = fmaf(xv[k], wh[k], ah);
        }

        if (r == 0) {                         // h == 0: r-gate irrelevant (gh==0)
            const float z  = __saturatef(0.2f * az + 0.5f);
            const float e  = __expf(2.0f * ah);
            const float hh = 1.0f - __fdividef(2.0f, e + 1.0f);
            const float hn = (1.0f - z) * hh;
            if ((sr >> 17) & 1)               // only if this id repeats later
                g_h[((size_t)b * TT + slot) * UU + u] = hn;
            if (t == TT - 1) g_hlast[(size_t)b * UU + u] = hn;
        } else {                              // deferred: also need ar; spill xz
            float ar = br;
            const float* wrp = wk + UU + u;
#pragma unroll
            for (int k = 0; k < FF; k++)
                ar = fmaf(xv[k], __ldg(wrp + k * G3), ar);
            float* p = g_xz + ((size_t)b * TT + t) * 3 * UU + u;
            p[0] = az; p[UU] = ar; p[2 * UU] = ah;
        }
    }
}

// ============================================================================
// tail: per row — all round>=1 steps processed in t order (dependencies are
// strictly increasing in t within a chain), GEMV against L1-resident packed
// rk (smem is tiny here, so L1D ~220KB holds all 192KB). Then the dense head.
// ============================================================================
__global__ __launch_bounds__(128)
void tail_k(const float* __restrict__ dw, const float* __restrict__ db,
            const float* __restrict__ ow, const float* __restrict__ ob,
            float* __restrict__ out)
{
    __shared__ float h_sh[UU];
    __shared__ int   meta_sh[TT];
    __shared__ float red[2];

    const int b = blockIdx.x, u = threadIdx.x;
    const int n = g_nrep[b];

    float hl = 0.0f;
    int   have = 0;

    if (n > 0) {
        if (u < TT) meta_sh[u] = g_meta[b * TT + u];
        __syncthreads();

        for (int t = 0; t < TT; t++) {
            const int m = meta_sh[t];
            if ((m >> 8) == 0) continue;      // uniform across block
            const int slot = m & 0xff;

            // all independent loads issued back-to-back, then publish h
            const float* p  = g_xz + ((size_t)b * TT + t) * 3 * UU + u;
            const float az  = p[0], ar = p[UU], ah = p[2 * UU];
            const float h_u = g_h[((size_t)b * TT + slot) * UU + u];
            h_sh[u] = h_u;
            __syncthreads();

            float gz = 0.0f, gr = 0.0f, gh = 0.0f;
#pragma unroll 4
            for (int k = 0; k < UU; k++) {
                const float  hv = h_sh[k];
                const float2 w  = __ldg(&g_rkzr[k * UU + u]);
                gz = fmaf(hv, w.x, gz);
                gr = fmaf(hv, w.y, gr);
                gh = fmaf(hv, __ldg(&g_rkh[k * UU + u]), gh);
            }

            const float z   = __saturatef(0.2f * (az + gz) + 0.5f);
            const float rr  = __saturatef(0.2f * (ar + gr) + 0.5f);
            const float pre = ah + rr * gh;
            const float e2  = __expf(2.0f * pre);
            const float hh  = 1.0f - __fdividef(2.0f, e2 + 1.0f);
            const float hn  = z * h_u + (1.0f - z) * hh;

            __syncthreads();                  // protect h_sh before next step
            g_h[((size_t)b * TT + slot) * UU + u] = hn;  // own lane only
            if (t == TT - 1) { hl = hn; have = 1; }
        }
    }

    if (!have) hl = g_hlast[(size_t)b * UU + u];
    h_sh[u] = hl;
    __syncthreads();

    if (u < 64) {
        float acc = db[u];
#pragma unroll 4
        for (int k = 0; k < UU; k++)
            acc = fmaf(h_sh[k], dw[k * 64 + u], acc);
        acc = fmaxf(acc, 0.0f) * ow[u];
#pragma unroll
        for (int o = 16; o; o >>= 1)
            acc += __shfl_down_sync(0xffffffff, acc, o);
        if ((u & 31) == 0) red[u >> 5] = acc;
    }
    __syncthreads();
    if (u == 0) {
        const float s = ob[0] + red[0] + red[1];
        out[b] = __fdividef(1.0f, 1.0f + __expf(-s));
    }
}

extern "C" void kernel_launch(void* const* d_in, const int* in_sizes, int n_in,
                              void* d_out, int out_size)
{
    const float* inputs      = (const float*)d_in[0];
    const float* sync_states = (const float*)d_in[1];
    const float* wk          = (const float*)d_in[2];
    const float* rk          = (const float*)d_in[3];
    const float* bias        = (const float*)d_in[4];
    const float* dw          = (const float*)d_in[5];
    const float* db          = (const float*)d_in[6];
    const float* ow          = (const float*)d_in[7];
    const float* ob          = (const float*)d_in[8];
    float* out = (float*)d_out;

    rnn_main<<<BB, 128>>>(inputs, sync_states, wk, rk, bias);
    tail_k<<<BB, 128>>>(dw, db, ow, ob, out);
}